// round 17
// baseline (speedup 1.0000x reference)
#include <cuda_runtime.h>
#include <cuda_bf16.h>
#include <cstdint>

// ---------------- problem constants ----------------
#define BATCH 2
#define LSEQ  8192
#define DMOD  768
#define NFFT  16384
#define LOGN  14
#define EMB   64
#define KP    (DMOD / 2)      // packed K pairs per row (384)

// ---------------- scratch ----------------
__device__ float  g_qT[BATCH * DMOD * LSEQ];
__device__ float  g_kT[BATCH * DMOD * LSEQ];
__device__ float  g_vT[BATCH * DMOD * LSEQ];
__device__ float  g_h [DMOD * LSEQ];
__device__ float2 g_Hf[DMOD * NFFT];           // filter spectrum, rev4-indexed
__device__ float2 g_tw[NFFT / 2];
// pre-split bf16 hi/lo packed-pair operand arrays
__device__ uint32_t g_xh [BATCH * LSEQ * KP], g_xl [BATCH * LSEQ * KP];   // x tokens
__device__ uint32_t g_wh [3 * DMOD * KP],     g_wl [3 * DMOD * KP];       // in_proj rows
__device__ uint32_t g_oh [DMOD * KP],         g_ol [DMOD * KP];           // out_proj rows
__device__ uint32_t g_ygh[BATCH * LSEQ * KP], g_ygl[BATCH * LSEQ * KP];   // gated output

__global__ void k_twiddle() {
    int i = blockIdx.x * blockDim.x + threadIdx.x;
    if (i < NFFT / 2) {
        double ang = -2.0 * 3.14159265358979323846 * (double)i / (double)NFFT;
        g_tw[i] = make_float2((float)cos(ang), (float)sin(ang));
    }
}

// ---------------- bf16 split ----------------
__device__ __forceinline__ void split_pack(float x, float y, uint32_t& hi, uint32_t& lo) {
    __nv_bfloat16 xh = __float2bfloat16(x);
    __nv_bfloat16 yh = __float2bfloat16(y);
    __nv_bfloat16 xl = __float2bfloat16(x - __bfloat162float(xh));
    __nv_bfloat16 yl = __float2bfloat16(y - __bfloat162float(yh));
    hi = ((uint32_t)__bfloat16_as_ushort(yh) << 16) | (uint32_t)__bfloat16_as_ushort(xh);
    lo = ((uint32_t)__bfloat16_as_ushort(yl) << 16) | (uint32_t)__bfloat16_as_ushort(xl);
}

__global__ void k_split(const float* __restrict__ src, uint32_t* __restrict__ dh,
                        uint32_t* __restrict__ dl, int npairs) {
    int i = blockIdx.x * blockDim.x + threadIdx.x;
    if (i < npairs) {
        float2 v = ((const float2*)src)[i];
        uint32_t h, l;
        split_pack(v.x, v.y, h, l);
        dh[i] = h;
        dl[i] = l;
    }
}

// ---------------- complex helpers ----------------
__device__ __forceinline__ float2 cmul(float2 a, float2 b) {
    return make_float2(a.x * b.x - a.y * b.y, a.x * b.y + a.y * b.x);
}
__device__ __forceinline__ float2 cmulc(float2 a, float2 b) {
    return make_float2(a.x * b.x + a.y * b.y, a.y * b.x - a.x * b.y);
}
__device__ __forceinline__ float2 cadd(float2 a, float2 b) { return make_float2(a.x + b.x, a.y + b.y); }
__device__ __forceinline__ float2 csub(float2 a, float2 b) { return make_float2(a.x - b.x, a.y - b.y); }

__device__ __forceinline__ int rev4_6(int x) {
    unsigned y = __brev((unsigned)x) >> 20;
    return (int)(((y & 0x555u) << 1) | ((y >> 1) & 0x555u));
}
__device__ __forceinline__ int SWZ(int e) {
    int h = (e >> 4) & 15;
    return (e & ~15) | ((e ^ (5 * h)) & 15);
}

__device__ __forceinline__ void bfly_fwd_w(float2& x0, float2& x1, float2& x2, float2& x3,
                                           float2 w, float2 w2, float2 w3) {
    float2 t0 = cadd(x0, x2), t1 = csub(x0, x2), t2 = cadd(x1, x3);
    float2 t3 = make_float2(x1.y - x3.y, x3.x - x1.x);
    x0 = cadd(t0, t2);
    x1 = cmul(cadd(t1, t3), w);
    x2 = cmul(csub(t0, t2), w2);
    x3 = cmul(csub(t1, t3), w3);
}
__device__ __forceinline__ void bfly_inv_w(float2& x0, float2& x1, float2& x2, float2& x3,
                                           float2 w, float2 w2, float2 w3) {
    float2 c1 = cmulc(x1, w), c2 = cmulc(x2, w2), c3 = cmulc(x3, w3);
    float2 v0 = cadd(x0, c2), v1 = cadd(c1, c3), v2 = csub(x0, c2), v3 = csub(c1, c3);
    x0 = cadd(v0, v1);
    x1 = make_float2(v2.x - v3.y, v2.y + v3.x);
    x2 = csub(v0, v1);
    x3 = make_float2(v2.x + v3.y, v2.y - v3.x);
}
__device__ __forceinline__ void r4_fwd_nw(float2* z) {
    float2 t0 = cadd(z[0], z[2]), t1 = csub(z[0], z[2]), t2 = cadd(z[1], z[3]);
    float2 t3 = make_float2(z[1].y - z[3].y, z[3].x - z[1].x);
    z[0] = cadd(t0, t2); z[1] = cadd(t1, t3); z[2] = csub(t0, t2); z[3] = csub(t1, t3);
}
__device__ __forceinline__ void r4_inv_nw(float2* z) {
    float2 v0 = cadd(z[0], z[2]), v1 = cadd(z[1], z[3]), v2 = csub(z[0], z[2]), v3 = csub(z[1], z[3]);
    z[0] = cadd(v0, v1);
    z[1] = make_float2(v2.x - v3.y, v2.y + v3.x);
    z[2] = csub(v0, v1);
    z[3] = make_float2(v2.x + v3.y, v2.y - v3.x);
}

template <int M4, int S>
__device__ __forceinline__ void fwd_pass2(float2* sm, int tid, int nthr) {
    for (int g = tid; g < 1024; g += nthr) {
        int j = g & (M4 - 1);
        int base = (g / M4) * (16 * M4) + j;
        float2 x[16];
#pragma unroll
        for (int t = 0; t < 16; t++) x[t] = sm[SWZ(base + t * M4)];
#pragma unroll
        for (int b = 0; b < 4; b++) {
            int e1 = (j + b * M4) << (2 * S);
            float2 w = g_tw[e1], w2 = g_tw[2 * e1], w3 = cmul(w, w2);
            bfly_fwd_w(x[b], x[4 + b], x[8 + b], x[12 + b], w, w2, w3);
        }
        {
            int e1 = j << (2 * (S + 1));
            float2 w = g_tw[e1], w2 = g_tw[2 * e1], w3 = cmul(w, w2);
#pragma unroll
            for (int a = 0; a < 4; a++)
                bfly_fwd_w(x[4 * a], x[4 * a + 1], x[4 * a + 2], x[4 * a + 3], w, w2, w3);
        }
#pragma unroll
        for (int t = 0; t < 16; t++) sm[SWZ(base + t * M4)] = x[t];
    }
    __syncthreads();
}

template <int M, int S>
__device__ __forceinline__ void inv_pass2(float2* sm, int tid, int nthr) {
    for (int g = tid; g < 1024; g += nthr) {
        int j = g & (M - 1);
        int base = (g / M) * (16 * M) + j;
        float2 x[16];
#pragma unroll
        for (int t = 0; t < 16; t++) x[t] = sm[SWZ(base + t * M)];
        {
            int e1 = j << (2 * (6 - S));
            float2 w = g_tw[e1], w2 = g_tw[2 * e1], w3 = cmul(w, w2);
#pragma unroll
            for (int b = 0; b < 4; b++)
                bfly_inv_w(x[4 * b], x[4 * b + 1], x[4 * b + 2], x[4 * b + 3], w, w2, w3);
        }
#pragma unroll
        for (int a = 0; a < 4; a++) {
            int e1 = (a * M + j) << (2 * (5 - S));
            float2 w = g_tw[e1], w2 = g_tw[2 * e1], w3 = cmul(w, w2);
            bfly_inv_w(x[a], x[4 + a], x[8 + a], x[12 + a], w, w2, w3);
        }
#pragma unroll
        for (int t = 0; t < 16; t++) sm[SWZ(base + t * M)] = x[t];
    }
    __syncthreads();
}

// ---------------- tensor-core GEMM (pre-split operands) ----------------
#define MMA_BF16(c, a, b)                                                     \
    asm volatile(                                                             \
        "mma.sync.aligned.m16n8k16.row.col.f32.bf16.bf16.f32 "                \
        "{%0,%1,%2,%3},{%4,%5,%6,%7},{%8,%9},{%0,%1,%2,%3};"                  \
        : "+f"(c[0]), "+f"(c[1]), "+f"(c[2]), "+f"(c[3])                      \
        : "r"(a[0]), "r"(a[1]), "r"(a[2]), "r"(a[3]), "r"(b[0]), "r"(b[1]))

#define LDSM4(r0, r1, r2, r3, addr)                                           \
    asm volatile("ldmatrix.sync.aligned.m8n8.x4.shared.b16 {%0,%1,%2,%3}, [%4];" \
                 : "=r"(r0), "=r"(r1), "=r"(r2), "=r"(r3) : "r"(addr))

#define BKP2 12
#define ROWB (BKP2 * 4)   // smem row stride in bytes (48)
// EPI=0 (qkv): A = g_wh/g_wl rows, B = g_xh/g_xl rows; base = token offset (j0).
// EPI=1 (out): A = g_ygh/g_ygl rows, B = g_oh/g_ol rows; base = row offset (i0).
template <int EPI>
__global__ __launch_bounds__(256) void k_gemm_tc(float* __restrict__ C, int basearg) {
    __shared__ uint32_t Ah[128][BKP2], Al[128][BKP2];
    __shared__ uint32_t Bh[128][BKP2], Bl[128][BKP2];

    const uint32_t* AhG = (EPI == 0) ? g_wh : g_ygh;
    const uint32_t* AlG = (EPI == 0) ? g_wl : g_ygl;
    const uint32_t* BhG = (EPI == 0) ? g_xh : g_oh;
    const uint32_t* BlG = (EPI == 0) ? g_xl : g_ol;

    const int i0 = blockIdx.y * 128 + ((EPI == 1) ? basearg : 0);
    const int j0 = blockIdx.x * 128 + ((EPI == 0) ? basearg : 0);
    const int tid = threadIdx.x;
    const int wid = tid >> 5;
    const int lane = tid & 31;
    const int g  = lane >> 2;
    const int tg = lane & 3;
    const int wm = wid >> 2;
    const int wn = wid & 3;

    const int r0  = tid >> 2;
    const int cc0 = (tid & 3) * 2;       // packed column {0,2,4,6}
    const uint32_t* Ah0 = AhG + (size_t)(i0 + r0) * KP + cc0;
    const uint32_t* Al0 = AlG + (size_t)(i0 + r0) * KP + cc0;
    const uint32_t* Ah1 = AhG + (size_t)(i0 + r0 + 64) * KP + cc0;
    const uint32_t* Al1 = AlG + (size_t)(i0 + r0 + 64) * KP + cc0;
    const uint32_t* Bh0 = BhG + (size_t)(j0 + r0) * KP + cc0;
    const uint32_t* Bl0 = BlG + (size_t)(j0 + r0) * KP + cc0;
    const uint32_t* Bh1 = BhG + (size_t)(j0 + r0 + 64) * KP + cc0;
    const uint32_t* Bl1 = BlG + (size_t)(j0 + r0 + 64) * KP + cc0;

    // ldmatrix lane addresses (bytes)
    const int arow = wm * 64 + (lane & 7) + ((lane >> 3) & 1) * 8;
    const int acol = ((lane >> 4) & 1) * 4;
    const uint32_t aOff = (uint32_t)(arow * ROWB + acol * 4);
    const uint32_t aHadr = (uint32_t)__cvta_generic_to_shared(&Ah[0][0]) + aOff;
    const uint32_t aLadr = (uint32_t)__cvta_generic_to_shared(&Al[0][0]) + aOff;
    const int brow = wn * 32 + (lane & 7) + ((lane >> 4) & 1) * 8;
    const int bcol = ((lane >> 3) & 1) * 4;
    const uint32_t bOff = (uint32_t)(brow * ROWB + bcol * 4);
    const uint32_t bHadr = (uint32_t)__cvta_generic_to_shared(&Bh[0][0]) + bOff;
    const uint32_t bLadr = (uint32_t)__cvta_generic_to_shared(&Bl[0][0]) + bOff;

    float c[4][4][4];
#pragma unroll
    for (int mi = 0; mi < 4; mi++)
#pragma unroll
        for (int ni = 0; ni < 4; ni++)
#pragma unroll
            for (int r = 0; r < 4; r++) c[mi][ni][r] = 0.f;

    uint2 a0h = *(const uint2*)(Ah0), a0l = *(const uint2*)(Al0);
    uint2 a1h = *(const uint2*)(Ah1), a1l = *(const uint2*)(Al1);
    uint2 b0h = *(const uint2*)(Bh0), b0l = *(const uint2*)(Bl0);
    uint2 b1h = *(const uint2*)(Bh1), b1l = *(const uint2*)(Bl1);

    for (int kb = 0; kb < KP; kb += 8) {       // 8 packed pairs = 16 floats per tile
        Ah[r0][cc0] = a0h.x; Ah[r0][cc0 + 1] = a0h.y;
        Al[r0][cc0] = a0l.x; Al[r0][cc0 + 1] = a0l.y;
        Ah[r0 + 64][cc0] = a1h.x; Ah[r0 + 64][cc0 + 1] = a1h.y;
        Al[r0 + 64][cc0] = a1l.x; Al[r0 + 64][cc0 + 1] = a1l.y;
        Bh[r0][cc0] = b0h.x; Bh[r0][cc0 + 1] = b0h.y;
        Bl[r0][cc0] = b0l.x; Bl[r0][cc0 + 1] = b0l.y;
        Bh[r0 + 64][cc0] = b1h.x; Bh[r0 + 64][cc0 + 1] = b1h.y;
        Bl[r0 + 64][cc0] = b1l.x; Bl[r0 + 64][cc0 + 1] = b1l.y;
        __syncthreads();

        if (kb + 8 < KP) {
            a0h = *(const uint2*)(Ah0 + kb + 8); a0l = *(const uint2*)(Al0 + kb + 8);
            a1h = *(const uint2*)(Ah1 + kb + 8); a1l = *(const uint2*)(Al1 + kb + 8);
            b0h = *(const uint2*)(Bh0 + kb + 8); b0l = *(const uint2*)(Bl0 + kb + 8);
            b1h = *(const uint2*)(Bh1 + kb + 8); b1l = *(const uint2*)(Bl1 + kb + 8);
        }

        uint32_t ah[4][4], al[4][4], bh[4][2], bl[4][2];
#pragma unroll
        for (int mi = 0; mi < 4; mi++) {
            LDSM4(ah[mi][0], ah[mi][1], ah[mi][2], ah[mi][3], aHadr + mi * 16 * ROWB);
            LDSM4(al[mi][0], al[mi][1], al[mi][2], al[mi][3], aLadr + mi * 16 * ROWB);
        }
        LDSM4(bh[0][0], bh[0][1], bh[1][0], bh[1][1], bHadr);
        LDSM4(bh[2][0], bh[2][1], bh[3][0], bh[3][1], bHadr + 16 * ROWB);
        LDSM4(bl[0][0], bl[0][1], bl[1][0], bl[1][1], bLadr);
        LDSM4(bl[2][0], bl[2][1], bl[3][0], bl[3][1], bLadr + 16 * ROWB);

#pragma unroll
        for (int mi = 0; mi < 4; mi++)
#pragma unroll
            for (int ni = 0; ni < 4; ni++) {
                MMA_BF16(c[mi][ni], ah[mi], bh[ni]);
                MMA_BF16(c[mi][ni], al[mi], bh[ni]);
                MMA_BF16(c[mi][ni], ah[mi], bl[ni]);
            }
        __syncthreads();
    }

#pragma unroll
    for (int mi = 0; mi < 4; mi++) {
#pragma unroll
        for (int ni = 0; ni < 4; ni++) {
            int rm0 = i0 + wm * 64 + mi * 16 + g;
            int rm1 = rm0 + 8;
            int cn  = j0 + wn * 32 + ni * 8 + 2 * tg;
            if (EPI == 0) {
                int part0 = rm0 / DMOD, dch0 = rm0 - part0 * DMOD;
                int part1 = rm1 / DMOD, dch1 = rm1 - part1 * DMOD;
                float* t0 = (part0 == 0) ? g_qT : (part0 == 1 ? g_kT : g_vT);
                float* t1 = (part1 == 0) ? g_qT : (part1 == 1 ? g_kT : g_vT);
                int bb = cn >> 13;
                int l  = cn & (LSEQ - 1);
                *(float2*)(t0 + ((size_t)bb * DMOD + dch0) * LSEQ + l) =
                    make_float2(c[mi][ni][0], c[mi][ni][1]);
                *(float2*)(t1 + ((size_t)bb * DMOD + dch1) * LSEQ + l) =
                    make_float2(c[mi][ni][2], c[mi][ni][3]);
            } else {
                *(float2*)(C + (size_t)rm0 * DMOD + cn) =
                    make_float2(c[mi][ni][0], c[mi][ni][1]);
                *(float2*)(C + (size_t)rm1 * DMOD + cn) =
                    make_float2(c[mi][ni][2], c[mi][ni][3]);
            }
        }
    }
}

// ---------------- hyena filter MLP + decay ----------------
#define FTL 32
__global__ __launch_bounds__(256) void k_filter(const float* __restrict__ w1, const float* __restrict__ b1,
                                                const float* __restrict__ w2, const float* __restrict__ b2,
                                                const float* __restrict__ w3, const float* __restrict__ b3,
                                                const float* __restrict__ ld) {
    __shared__ float ws [EMB][EMB + 1];
    __shared__ float pe [FTL][EMB + 1];
    __shared__ float h1s[FTL][EMB + 1];
    __shared__ float h2s[FTL][EMB + 1];
    const int l0 = blockIdx.x * FTL;
    const int tid = threadIdx.x;
    const float TWO_PI = 6.2831853071795864769f;
    const float inv = 1.0f / (float)(LSEQ - 1);

    for (int idx = tid; idx < EMB * EMB; idx += 256)
        ws[idx >> 6][idx & 63] = w1[idx];
    for (int idx = tid; idx < FTL * EMB; idx += 256) {
        int li = idx >> 6, e = idx & 63;
        float t = (float)(l0 + li) * inv;
        pe[li][e] = (e < 32) ? sinf(t * TWO_PI * (float)(e + 1))
                             : cosf(t * TWO_PI * (float)(e - 31));
    }
    __syncthreads();
    for (int idx = tid; idx < FTL * EMB; idx += 256) {
        int li = idx >> 6, e = idx & 63;
        float s = b1[e];
#pragma unroll 16
        for (int cc = 0; cc < EMB; cc++) s += pe[li][cc] * ws[e][cc];
        h1s[li][e] = s / (1.f + __expf(-s));
    }
    __syncthreads();
    for (int idx = tid; idx < EMB * EMB; idx += 256)
        ws[idx >> 6][idx & 63] = w2[idx];
    __syncthreads();
    for (int idx = tid; idx < FTL * EMB; idx += 256) {
        int li = idx >> 6, e = idx & 63;
        float s = b2[e];
#pragma unroll 16
        for (int cc = 0; cc < EMB; cc++) s += h1s[li][cc] * ws[e][cc];
        h2s[li][e] = s / (1.f + __expf(-s));
    }
    __syncthreads();
    for (int d = tid; d < DMOD; d += 256) {
        float a = fabsf(ld[d]);
        float* outp = g_h + (size_t)d * LSEQ + l0;
        if (a * (float)l0 > 100.f) {
#pragma unroll
            for (int li = 0; li < FTL; li++) outp[li] = 0.f;
            continue;
        }
        float acc[FTL];
#pragma unroll
        for (int li = 0; li < FTL; li++) acc[li] = 0.f;
        const float* w3r = w3 + d * EMB;
#pragma unroll 8
        for (int e = 0; e < EMB; e++) {
            float wv = w3r[e];
#pragma unroll
            for (int li = 0; li < FTL; li++) acc[li] += h2s[li][e] * wv;
        }
        float b3d = b3[d];
        float dec  = __expf(-a * (float)l0);
        float step = __expf(-a);
#pragma unroll
        for (int li = 0; li < FTL; li++) {
            outp[li] = (acc[li] + b3d) * dec;
            dec *= step;
        }
    }
}

// ---------------- filter spectrum ----------------
__global__ __launch_bounds__(512) void k_fft_h() {
    extern __shared__ float2 sm[];
    const int c = blockIdx.x;
    const int d0 = 2 * c, d1 = 2 * c + 1;
    const int tid = threadIdx.x, nthr = blockDim.x;
    const float* s0 = g_h + (size_t)d0 * LSEQ;
    const float* s1 = g_h + (size_t)d1 * LSEQ;

    for (int j = tid; j < 1024; j += nthr) {
        float2 x[16];
#pragma unroll
        for (int t = 0; t < 8; t++) {
            int l = j + t * 1024;
            x[t] = make_float2(s0[l], s1[l]);
        }
#pragma unroll
        for (int b = 0; b < 4; b++) {
            int e1 = j + b * 1024;
            float2 w = g_tw[e1], w2 = g_tw[2 * e1], w3 = cmul(w, w2);
            float2 a0 = x[b], a1 = x[4 + b];
            x[b]      = cadd(a0, a1);
            x[4 + b]  = cmul(make_float2(a0.x + a1.y, a0.y - a1.x), w);
            x[8 + b]  = cmul(csub(a0, a1), w2);
            x[12 + b] = cmul(make_float2(a0.x - a1.y, a0.y + a1.x), w3);
        }
        {
            int e1 = j << 2;
            float2 w = g_tw[e1], w2 = g_tw[2 * e1], w3 = cmul(w, w2);
#pragma unroll
            for (int a = 0; a < 4; a++)
                bfly_fwd_w(x[4 * a], x[4 * a + 1], x[4 * a + 2], x[4 * a + 3], w, w2, w3);
        }
#pragma unroll
        for (int t = 0; t < 16; t++) sm[SWZ(j + t * 1024)] = x[t];
    }
    __syncthreads();

    fwd_pass2<64, 2>(sm, tid, nthr);
    fwd_pass2<4, 4>(sm, tid, nthr);

    float2* Ha = g_Hf + (size_t)d0 * NFFT;
    float2* Hb = g_Hf + (size_t)d1 * NFFT;
    for (int i = tid; i < 4096; i += nthr) {
        int r = rev4_6(i);
        int i2 = (r == 0) ? 0 : rev4_6(4096 - r);
        if (i2 < i) continue;
        float2 z[4], zz[4];
#pragma unroll
        for (int t = 0; t < 4; t++) z[t] = sm[SWZ(4 * i + t)];
        r4_fwd_nw(z);
        bool self = (i2 == i);
        if (!self) {
#pragma unroll
            for (int t = 0; t < 4; t++) zz[t] = sm[SWZ(4 * i2 + t)];
            r4_fwd_nw(zz);
        }
#pragma unroll
        for (int t = 0; t < 4; t++) {
            int tp = (i == 0) ? ((4 - t) & 3) : (3 - t);
            float2 z1 = z[t];
            float2 z2 = self ? z[tp] : zz[tp];
            float2 ha = make_float2(0.5f * (z1.x + z2.x), 0.5f * (z1.y - z2.y));
            float2 hb = make_float2(0.5f * (z1.y + z2.y), 0.5f * (z2.x - z1.x));
            int p = 4 * i + t;
            int q = 4 * i2 + tp;
            Ha[p] = ha;
            Hb[p] = hb;
            Ha[q] = make_float2(ha.x, -ha.y);
            Hb[q] = make_float2(hb.x, -hb.y);
        }
    }
}

// ---- fused fftconv (writes gated output pre-split as bf16 hi/lo pairs) ----
__global__ __launch_bounds__(512) void k_fftconv(const float* __restrict__ skw, const float* __restrict__ skb,
                                                 const float* __restrict__ svw, const float* __restrict__ svb,
                                                 int bcbase) {
    extern __shared__ float2 sm[];
    const int bc = blockIdx.x + bcbase;
    const int b = bc / (DMOD / 2);
    const int c = bc - b * (DMOD / 2);
    const int d0 = 2 * c, d1 = 2 * c + 1;
    const int tid = threadIdx.x, nthr = blockDim.x;

    const float* k0 = g_kT + ((size_t)b * DMOD + d0) * LSEQ;
    const float* k1 = g_kT + ((size_t)b * DMOD + d1) * LSEQ;
    const float* v0 = g_vT + ((size_t)b * DMOD + d0) * LSEQ;
    const float* v1 = g_vT + ((size_t)b * DMOD + d1) * LSEQ;

    float kw00 = skw[d0 * 3], kw01 = skw[d0 * 3 + 1], kw02 = skw[d0 * 3 + 2], kb0 = skb[d0];
    float vw00 = svw[d0 * 3], vw01 = svw[d0 * 3 + 1], vw02 = svw[d0 * 3 + 2], vb0 = svb[d0];
    float kw10 = skw[d1 * 3], kw11 = skw[d1 * 3 + 1], kw12 = skw[d1 * 3 + 2], kb1 = skb[d1];
    float vw10 = svw[d1 * 3], vw11 = svw[d1 * 3 + 1], vw12 = svw[d1 * 3 + 2], vb1 = svb[d1];

#define UPAIR(l, out)                                                                   \
    {                                                                                   \
        int _l = (l);                                                                   \
        float ka2 = k0[_l];                                                             \
        float ka1 = (_l >= 1) ? k0[_l - 1] : 0.f;                                       \
        float ka0 = (_l >= 2) ? k0[_l - 2] : 0.f;                                       \
        float va2 = v0[_l];                                                             \
        float va1 = (_l >= 1) ? v0[_l - 1] : 0.f;                                       \
        float va0 = (_l >= 2) ? v0[_l - 2] : 0.f;                                       \
        float u0 = (kw00 * ka0 + kw01 * ka1 + kw02 * ka2 + kb0) *                       \
                   (vw00 * va0 + vw01 * va1 + vw02 * va2 + vb0);                        \
        float kb2_ = k1[_l];                                                            \
        float kb1_ = (_l >= 1) ? k1[_l - 1] : 0.f;                                      \
        float kb0_ = (_l >= 2) ? k1[_l - 2] : 0.f;                                      \
        float vb2_ = v1[_l];                                                            \
        float vb1_ = (_l >= 1) ? v1[_l - 1] : 0.f;                                      \
        float vb0_ = (_l >= 2) ? v1[_l - 2] : 0.f;                                      \
        float u1 = (kw10 * kb0_ + kw11 * kb1_ + kw12 * kb2_ + kb1) *                    \
                   (vw10 * vb0_ + vw11 * vb1_ + vw12 * vb2_ + vb1);                     \
        out = make_float2(u0, u1);                                                      \
    }

    for (int j = tid; j < 1024; j += nthr) {
        float2 x[16];
#pragma unroll
        for (int t = 0; t < 8; t++) { UPAIR(j + t * 1024, x[t]); }
#pragma unroll
        for (int bb2 = 0; bb2 < 4; bb2++) {
            int e1 = j + bb2 * 1024;
            float2 w = g_tw[e1], w2 = g_tw[2 * e1], w3 = cmul(w, w2);
            float2 a0 = x[bb2], a1 = x[4 + bb2];
            x[bb2]      = cadd(a0, a1);
            x[4 + bb2]  = cmul(make_float2(a0.x + a1.y, a0.y - a1.x), w);
            x[8 + bb2]  = cmul(csub(a0, a1), w2);
            x[12 + bb2] = cmul(make_float2(a0.x - a1.y, a0.y + a1.x), w3);
        }
        {
            int e1 = j << 2;
            float2 w = g_tw[e1], w2 = g_tw[2 * e1], w3 = cmul(w, w2);
#pragma unroll
            for (int a = 0; a < 4; a++)
                bfly_fwd_w(x[4 * a], x[4 * a + 1], x[4 * a + 2], x[4 * a + 3], w, w2, w3);
        }
#pragma unroll
        for (int t = 0; t < 16; t++) sm[SWZ(j + t * 1024)] = x[t];
    }
#undef UPAIR
    __syncthreads();

    fwd_pass2<64, 2>(sm, tid, nthr);
    fwd_pass2<4, 4>(sm, tid, nthr);

    {
        const float2* Ha = g_Hf + (size_t)d0 * NFFT;
        const float2* Hb = g_Hf + (size_t)d1 * NFFT;
        const float hscale = 0.5f / (float)NFFT;
        for (int i = tid; i < 4096; i += nthr) {
            int r = rev4_6(i);
            int i2 = (r == 0) ? 0 : rev4_6(4096 - r);
            if (i2 < i) continue;
            float2 z[4], zz[4];
#pragma unroll
            for (int t = 0; t < 4; t++) z[t] = sm[SWZ(4 * i + t)];
            r4_fwd_nw(z);
            bool self = (i2 == i);
            if (!self) {
#pragma unroll
                for (int t = 0; t < 4; t++) zz[t] = sm[SWZ(4 * i2 + t)];
                r4_fwd_nw(zz);
            }
            float2 o1[4], o2[4];
#pragma unroll
            for (int t = 0; t < 4; t++) {
                int tp = (i == 0) ? ((4 - t) & 3) : (3 - t);
                float2 z1 = z[t];
                float2 z2 = self ? z[tp] : zz[tp];
                float2 za = make_float2(hscale * (z1.x + z2.x), hscale * (z1.y - z2.y));
                float2 zb = make_float2(hscale * (z1.y + z2.y), hscale * (z2.x - z1.x));
                int p = 4 * i + t;
                float2 ya = cmul(za, Ha[p]);
                float2 yb = cmul(zb, Hb[p]);
                o1[t]  = make_float2(ya.x - yb.y, ya.y + yb.x);
                o2[tp] = make_float2(ya.x + yb.y, yb.x - ya.y);
            }
            r4_inv_nw(o1);
#pragma unroll
            for (int t = 0; t < 4; t++) sm[SWZ(4 * i + t)] = o1[t];
            if (!self) {
                r4_inv_nw(o2);
#pragma unroll
                for (int t = 0; t < 4; t++) sm[SWZ(4 * i2 + t)] = o2[t];
            }
        }
    }
    __syncthreads();

    inv_pass2<4, 1>(sm, tid, nthr);
    inv_pass2<64, 3>(sm, tid, nthr);

    const float* q0 = g_qT + ((size_t)b * DMOD + d0) * LSEQ;
    const float* q1 = g_qT + ((size_t)b * DMOD + d1) * LSEQ;
    for (int j = tid; j < 1024; j += nthr) {
        float2 x[16];
#pragma unroll
        for (int t = 0; t < 16; t++) x[t] = sm[SWZ(j + t * 1024)];
        {
            int e1 = j << 2;
            float2 w = g_tw[e1], w2 = g_tw[2 * e1], w3 = cmul(w, w2);
#pragma unroll
            for (int bb2 = 0; bb2 < 4; bb2++)
                bfly_inv_w(x[4 * bb2], x[4 * bb2 + 1], x[4 * bb2 + 2], x[4 * bb2 + 3], w, w2, w3);
        }
#pragma unroll
        for (int a = 0; a < 4; a++) {
            int e1 = a * 1024 + j;
            float2 w = g_tw[e1], w2 = g_tw[2 * e1], w3 = cmul(w, w2);
            float2 c1 = cmulc(x[4 + a], w);
            float2 c2 = cmulc(x[8 + a], w2);
            float2 c3 = cmulc(x[12 + a], w3);
            float2 v0 = cadd(x[a], c2);
            float2 v1 = cadd(c1, c3);
            float2 v2 = csub(x[a], c2);
            float2 v3 = csub(c1, c3);
            float2 y0 = cadd(v0, v1);
            float2 y1 = make_float2(v2.x - v3.y, v2.y + v3.x);
            {
                int l = j + a * 1024;
                float qa = q0[l], qb = q1[l];
                float ga = qa / (1.f + __expf(-qa));
                float gb = qb / (1.f + __expf(-qb));
                uint32_t h, lo;
                split_pack(ga * y0.x, gb * y0.y, h, lo);
                size_t idx = (size_t)(b * LSEQ + l) * KP + c;
                g_ygh[idx] = h;
                g_ygl[idx] = lo;
            }
            {
                int l = j + a * 1024 + 4096;
                float qa = q0[l], qb = q1[l];
                float ga = qa / (1.f + __expf(-qa));
                float gb = qb / (1.f + __expf(-qb));
                uint32_t h, lo;
                split_pack(ga * y1.x, gb * y1.y, h, lo);
                size_t idx = (size_t)(b * LSEQ + l) * KP + c;
                g_ygh[idx] = h;
                g_ygl[idx] = lo;
            }
        }
    }
}

// --------- launch: pre-split operands + batch-split pipeline ---------
extern "C" void kernel_launch(void* const* d_in, const int* in_sizes, int n_in,
                              void* d_out, int out_size) {
    const float* x        = (const float*)d_in[0];
    const float* in_proj  = (const float*)d_in[1];
    const float* sck_w    = (const float*)d_in[2];
    const float* sck_b    = (const float*)d_in[3];
    const float* scv_w    = (const float*)d_in[4];
    const float* scv_b    = (const float*)d_in[5];
    const float* mlp_w1   = (const float*)d_in[6];
    const float* mlp_b1   = (const float*)d_in[7];
    const float* mlp_w2   = (const float*)d_in[8];
    const float* mlp_b2   = (const float*)d_in[9];
    const float* mlp_w3   = (const float*)d_in[10];
    const float* mlp_b3   = (const float*)d_in[11];
    const float* log_dec  = (const float*)d_in[12];
    const float* out_proj = (const float*)d_in[13];
    float* out = (float*)d_out;

    static cudaStream_t s2 = nullptr;
    static cudaEvent_t eFork = nullptr, e0 = nullptr, e1 = nullptr, ec0 = nullptr, ec1 = nullptr;
    static uint32_t *p_xh = nullptr, *p_xl = nullptr, *p_wh = nullptr, *p_wl = nullptr,
                    *p_oh = nullptr, *p_ol = nullptr;
    static int smem_set = 0;
    const int smem_fft = NFFT * sizeof(float2);   // 128 KB
    if (!s2) {
        cudaStreamCreateWithFlags(&s2, cudaStreamNonBlocking);
        cudaEventCreateWithFlags(&eFork, cudaEventDisableTiming);
        cudaEventCreateWithFlags(&e0, cudaEventDisableTiming);
        cudaEventCreateWithFlags(&e1, cudaEventDisableTiming);
        cudaEventCreateWithFlags(&ec0, cudaEventDisableTiming);
        cudaEventCreateWithFlags(&ec1, cudaEventDisableTiming);
        cudaGetSymbolAddress((void**)&p_xh, g_xh);
        cudaGetSymbolAddress((void**)&p_xl, g_xl);
        cudaGetSymbolAddress((void**)&p_wh, g_wh);
        cudaGetSymbolAddress((void**)&p_wl, g_wl);
        cudaGetSymbolAddress((void**)&p_oh, g_oh);
        cudaGetSymbolAddress((void**)&p_ol, g_ol);
    }
    if (!smem_set) {
        cudaFuncSetAttribute(k_fft_h,   cudaFuncAttributeMaxDynamicSharedMemorySize, smem_fft);
        cudaFuncSetAttribute(k_fftconv, cudaFuncAttributeMaxDynamicSharedMemorySize, smem_fft);
        smem_set = 1;
    }

    // fork: side stream does filter chain + out_proj split
    cudaEventRecord(eFork, 0);
    cudaStreamWaitEvent(s2, eFork, 0);
    k_twiddle<<<16, 512, 0, s2>>>();
    k_split<<<(DMOD * KP + 511) / 512, 512, 0, s2>>>(out_proj, p_oh, p_ol, DMOD * KP);
    k_filter<<<LSEQ / FTL, 256, 0, s2>>>(mlp_w1, mlp_b1, mlp_w2, mlp_b2, mlp_w3, mlp_b3, log_dec);
    k_fft_h<<<DMOD / 2, 512, smem_fft, s2>>>();

    // main: split GEMM inputs, then qkv halves
    k_split<<<(BATCH * LSEQ * KP + 511) / 512, 512>>>(x, p_xh, p_xl, BATCH * LSEQ * KP);
    k_split<<<(3 * DMOD * KP + 511) / 512, 512>>>(in_proj, p_wh, p_wl, 3 * DMOD * KP);

    k_gemm_tc<0><<<dim3(64, 18), 256>>>(nullptr, 0);
    cudaEventRecord(e0, 0);
    cudaStreamWaitEvent(s2, e0, 0);
    k_fftconv<<<DMOD / 2, 512, smem_fft, s2>>>(sck_w, sck_b, scv_w, scv_b, 0);
    cudaEventRecord(ec0, s2);

    k_gemm_tc<0><<<dim3(64, 18), 256>>>(nullptr, 8192);
    cudaEventRecord(e1, 0);
    cudaStreamWaitEvent(s2, e1, 0);
    k_fftconv<<<DMOD / 2, 512, smem_fft, s2>>>(sck_w, sck_b, scv_w, scv_b, DMOD / 2);
    cudaEventRecord(ec1, s2);

    cudaStreamWaitEvent(0, ec0, 0);
    k_gemm_tc<1><<<dim3(6, 64), 256>>>(out, 0);
    cudaStreamWaitEvent(0, ec1, 0);
    k_gemm_tc<1><<<dim3(6, 64), 256>>>(out, 8192);
}